// round 17
// baseline (speedup 1.0000x reference)
#include <cuda_runtime.h>
#include <cuda_bf16.h>

// Problem constants (fixed by the reference setup).
#define BB   256
#define NN   4000
#define GG   50
#define M_TOT (BB * NN)      // 1,024,000 elements
#define TMAX  (BB * GG)      // 12,800 max TPs per threshold
#define NBKT  4096           // 12-bit value buckets
#define NW    125            // 32-bit words covering NN proposals (125*32 == 4000)
#define GRID  148            // one block per SM; all co-resident (1 block/SM)

// ----------------------------------------------------------------------------
// Device scratch (static globals — zero-initialized at load; every counter is
// restored to zero within the launch, so graph replays are deterministic)
// ----------------------------------------------------------------------------
__device__ unsigned long long g_list[2][TMAX];       // compacted TP keys (unordered)
__device__ unsigned long long g_sorted[2][TMAX];     // fully sorted ascending keys
__device__ int g_T[2];                               // TP counts
__device__ __align__(16) int g_bcount[2][NBKT];      // bucket counts (filled by greedy)
__device__ int g_boff[2][NBKT + 1];                  // bucket offsets
__device__ int g_c[2][TMAX + 1];                     // lower-bound histogram
__device__ int g_bar[3], g_pass[3];                  // grid barrier state (self-resetting)

// ----------------------------------------------------------------------------
// Software grid barrier. Correct because ALL GRID blocks are co-resident
// (grid == #SMs, 1 block/SM). Last block to PASS the barrier resets the
// counters (everyone else has already stopped touching them) -> replay-safe.
// ----------------------------------------------------------------------------
__device__ __forceinline__ void grid_sync_idx(int i) {
    __syncthreads();
    if (threadIdx.x == 0) {
        __threadfence();                               // publish this block's writes
        atomicAdd(&g_bar[i], 1);
        while (atomicAdd(&g_bar[i], 0) < GRID) __nanosleep(64);
        int p = atomicAdd(&g_pass[i], 1);
        if (p == GRID - 1) { g_bar[i] = 0; g_pass[i] = 0; __threadfence(); }
    }
    __syncthreads();
}

// ----------------------------------------------------------------------------
// Key: ascending key == (conf descending, index ascending).
// Layout: [conf-ord 32][idx 20][bucket 12]; bucket is monotone with the key.
// ----------------------------------------------------------------------------
__device__ __forceinline__ unsigned int ford(float f) {
    unsigned int u = __float_as_uint(f);
    return (u & 0x80000000u) ? ~u : (u | 0x80000000u);   // ascending float order
}
__device__ __forceinline__ int bucket_of(float conf) {
    int bi = (int)(conf * 4096.0f);
    bi = bi < 0 ? 0 : (bi > 4095 ? 4095 : bi);
    return 4095 - bi;                                     // higher conf -> smaller bucket
}
__device__ __forceinline__ unsigned long long make_key(float conf, int idx) {
    unsigned int kh = ~ford(conf);                        // ascending kh == descending conf
    return ((unsigned long long)kh << 32)
         | ((unsigned long long)(unsigned int)idx << 12)
         | (unsigned long long)bucket_of(conf);
}

// ============================================================================
// Single fused kernel: greedy -> [bar] -> sort -> [bar] -> hist -> [bar] -> final
// Dynamic SMEM = 135,184 B (max over phases), overlaid per phase.
// ============================================================================
__global__ void __launch_bounds__(1024) k_all(const float2* __restrict__ segs,
                                              const float2* __restrict__ gts,
                                              const float*  __restrict__ scores,
                                              float* __restrict__ out) {
    const int tid = threadIdx.x;
    const int lane = tid & 31, warp = tid >> 5;           // 32 warps
    extern __shared__ int sm[];                           // 135,184 B dynamic

    // ---- static shared (union-free; small) ----
    __shared__ float4 sgt[GG];
    __shared__ float2 raw[GG];
    __shared__ unsigned int suse[2][NW];
    __shared__ int s_tab[64];
    __shared__ int s_maxlen;
    __shared__ int s_cnt[2], s_base[2];
    __shared__ int s_cnt64[64], s_off64[64], s_fill64[64];
    __shared__ int wtot[32];
    __shared__ float  wmax[32];
    __shared__ double wdbl[32];
    __shared__ float  s_suf[1024];
    __shared__ float  s_gmax;

    // ========================= PHASE 1: GREEDY ==============================
    // SMEM overlay: pot[12500 ints] | sxy[NN] float2 @byte 50000 | sn[NN] u16 @82000
    {
        unsigned int* pot = (unsigned int*)sm;
        float2*         sxy = (float2*)(sm + 2 * GG * NW);
        unsigned short* sn  = (unsigned short*)(sxy + NN);

        // zero the lower-bound histogram once (distributed over the grid)
        for (int i = blockIdx.x * 1024 + tid; i < 2 * (TMAX + 1); i += GRID * 1024)
            ((int*)g_c)[i] = 0;

        for (int b = blockIdx.x; b < BB; b += GRID) {
            // per-batch resets
            for (int i = tid; i < 2 * GG * NW; i += 1024) pot[i] = 0u;
            if (tid == 0) s_maxlen = 0;
            if (tid < 2) s_cnt[tid] = 0;
            if (tid < 64) { s_cnt64[tid] = 0; s_fill64[tid] = 0; }
            if (tid < GG) raw[tid] = gts[b * GG + tid];
            __syncthreads();

            // sort gts by start (rank sort, stable on ties) + max length
            if (tid < GG) {
                float2 t = raw[tid];
                int r = 0;
                for (int j = 0; j < GG; ++j) {
                    float xj = raw[j].x;
                    r += (xj < t.x) || (xj == t.x && j < tid);
                }
                sgt[r] = make_float4(t.x, t.y, t.y - t.x, __int_as_float(tid));
                atomicMax(&s_maxlen, __float_as_int(t.y - t.x));
            }

            // counting-sort pass A: proposal-start bin counts (64 bins)
            for (int n = tid; n < NN; n += 1024) {
                float sx = segs[b * NN + n].x;
                int bq = (int)(sx * 64.0f);
                bq = bq < 0 ? 0 : (bq > 63 ? 63 : bq);
                atomicAdd(&s_cnt64[bq], 1);
            }
            __syncthreads();

            // gt start table + 64-bin exclusive scan (warp 0)
            if (tid < 64) {
                float thr = (float)tid * (1.0f / 64.0f);
                int j = 0;
                while (j < GG && sgt[j].x < thr) ++j;
                s_tab[tid] = j;
            }
            if (warp == 0) {
                int c0 = s_cnt64[lane * 2], c1 = s_cnt64[lane * 2 + 1];
                int s2 = c0 + c1, v = s2;
#pragma unroll
                for (int d = 1; d < 32; d <<= 1) {
                    int o = __shfl_up_sync(0xFFFFFFFFu, v, d);
                    if (lane >= d) v += o;
                }
                int excl = v - s2;
                s_off64[lane * 2] = excl;
                s_off64[lane * 2 + 1] = excl + c0;
            }
            __syncthreads();
            const float maxlg = __int_as_float(s_maxlen);

            // counting-sort pass B: scatter proposals into start-sorted order
            for (int n = tid; n < NN; n += 1024) {
                float2 s = segs[b * NN + n];
                int bq = (int)(s.x * 64.0f);
                bq = bq < 0 ? 0 : (bq > 63 ? 63 : bq);
                int pos = s_off64[bq] + atomicAdd(&s_fill64[bq], 1);
                sxy[pos] = s;
                sn[pos] = (unsigned short)n;
            }
            __syncthreads();

            // candidate evaluation: warp-uniform gt window over sorted chunks
            for (int ch = warp; ch < NW; ch += 32) {
                int i = ch * 32 + lane;
                float2 s = sxy[i];
                int n = sn[i];
                float la = s.y - s.x;
                int wn = n >> 5;
                unsigned int bitn = 1u << (n & 31);

                float xlo = s.x - maxlg;
                int q = (int)(xlo * 64.0f) - 1;
                q = q < 0 ? 0 : (q > 63 ? 63 : q);
                int jmin = __reduce_min_sync(0xFFFFFFFFu, s_tab[q]);
                int symax_i = __reduce_max_sync(0xFFFFFFFFu, __float_as_int(s.y));
                float symax = __int_as_float(symax_i);

                for (int j = jmin; j < GG; ++j) {
                    float4 t = sgt[j];
                    if (t.x >= symax) break;
                    float inter = fminf(s.y, t.y) - fmaxf(s.x, t.x);
                    float ssum  = la + t.z;
                    int g = __float_as_int(t.w);
                    if (3.0f * inter > ssum)         atomicOr(&pot[g * NW + wn], bitn);
                    if (7.0f * inter > 3.0f * ssum)  atomicOr(&pot[(GG + g) * NW + wn], bitn);
                }
            }
            __syncthreads();

            // greedy claims: one warp per threshold, used bits in registers
            if (warp < 2) {
                const int z = warp;
                unsigned int usedreg[4] = {0u, 0u, 0u, 0u};
                const unsigned int* P = pot + z * GG * NW;
                for (int g = 0; g < GG; ++g) {
                    unsigned int best = 0xFFFFFFFFu;
#pragma unroll
                    for (int s = 0; s < 4; ++s) {
                        int w = s * 32 + lane;
                        if (w < NW) {
                            unsigned int c = P[g * NW + w] & ~usedreg[s];
                            if (c) best = min(best, (unsigned int)(w * 32 + __ffs(c) - 1));
                        }
                    }
                    unsigned int m = __reduce_min_sync(0xFFFFFFFFu, best);
                    if (m != 0xFFFFFFFFu) {
                        int wm = (int)(m >> 5);
                        if ((wm & 31) == lane) usedreg[wm >> 5] |= 1u << (m & 31);
                    }
                }
#pragma unroll
                for (int s = 0; s < 4; ++s) {
                    int w = s * 32 + lane;
                    if (w < NW) suse[z][w] = usedreg[s];
                }
            }
            __syncthreads();

            // emit TP keys: block-aggregated reservation (1 global atomic per z)
            int z = -1, w = 0, cnt = 0, lbase = 0;
            unsigned int word = 0;
            if (tid < 2 * NW) {
                z = tid / NW; w = tid % NW;
                word = suse[z][w];
                cnt = __popc(word);
                if (cnt) lbase = atomicAdd(&s_cnt[z], cnt);
            }
            __syncthreads();
            if (tid < 2) s_base[tid] = s_cnt[tid] ? atomicAdd(&g_T[tid], s_cnt[tid]) : 0;
            __syncthreads();
            if (cnt) {
                int p = s_base[z] + lbase;
                while (word) {
                    int bit = __ffs(word) - 1;
                    word &= word - 1;
                    int idx = b * NN + w * 32 + bit;
                    unsigned long long key = make_key(scores[idx], idx);
                    g_list[z][p++] = key;
                    atomicAdd(&g_bcount[z][(int)(key & 0xFFFull)], 1);
                }
            }
            __syncthreads();                               // pot reused next batch round
        }
    }
    grid_sync_idx(0);

    // ========================= PHASE 2: SORT (blocks 0,1) ===================
    // SMEM overlay (ints): off[0..NBKT] | pad | fill[NBKT] | skeys (8B-aligned)
    if (blockIdx.x < 2) {
        const int z = blockIdx.x;
        int* off  = sm;
        int* fill = sm + NBKT + 4;                        // byte 16400 = 16-aligned
        unsigned long long* skeys = (unsigned long long*)(sm + 2 * NBKT + 4);

        int T = g_T[z];

        int4* bc = (int4*)&g_bcount[z][0];
        int4 c4 = bc[tid];
        bc[tid] = make_int4(0, 0, 0, 0);
        ((int4*)fill)[tid] = make_int4(0, 0, 0, 0);

        int loc[4]; int s = 0;
        loc[0] = s; s += c4.x; loc[1] = s; s += c4.y;
        loc[2] = s; s += c4.z; loc[3] = s; s += c4.w;
        int v = s;
#pragma unroll
        for (int d = 1; d < 32; d <<= 1) {
            int o = __shfl_up_sync(0xFFFFFFFFu, v, d);
            if (lane >= d) v += o;
        }
        if (lane == 31) wtot[warp] = v;
        __syncthreads();
        if (warp == 0) {
            int w = wtot[lane], wi = w;
#pragma unroll
            for (int d = 1; d < 32; d <<= 1) {
                int o = __shfl_up_sync(0xFFFFFFFFu, wi, d);
                if (lane >= d) wi += o;
            }
            wtot[lane] = wi - w;
        }
        __syncthreads();
        int excl = wtot[warp] + (v - s);
        int base = tid * 4;
#pragma unroll
        for (int j = 0; j < 4; ++j) off[base + j] = excl + loc[j];
        if (tid == 1023) off[NBKT] = excl + s;
        __syncthreads();

        for (int i = tid; i < T; i += 1024) {
            unsigned long long k = g_list[z][i];
            int bk = (int)(k & 0xFFFull);
            skeys[off[bk] + atomicAdd(&fill[bk], 1)] = k;
        }
        __syncthreads();

        for (int bk = tid; bk < NBKT; bk += 1024) {
            int st = off[bk], en = off[bk + 1];
            for (int i = st; i < en; ++i) {
                unsigned long long k = skeys[i];
                int r = 0;
                for (int j = st; j < en; ++j) r += (skeys[j] < k) ? 1 : 0;
                g_sorted[z][st + r] = k;
            }
        }
        for (int i = tid; i <= NBKT; i += 1024) g_boff[z][i] = off[i];
    }
    grid_sync_idx(1);

    // ========================= PHASE 3: HIST ================================
    // SMEM overlay: soff[0..NBKT] | sk[TMAX] (8B-aligned at int NBKT+2)
    {
        const int z = blockIdx.x & 1;                     // 74 blocks per threshold
        const int part = blockIdx.x >> 1;
        int* soff = sm;
        unsigned long long* sk = (unsigned long long*)(sm + NBKT + 2);
        int T = g_T[z];
        for (int i = tid; i < T; i += 1024) sk[i] = g_sorted[z][i];
        for (int i = tid; i <= NBKT; i += 1024) soff[i] = g_boff[z][i];
        __syncthreads();

        const int stride = 74 * 1024;
        for (int idx = part * 1024 + tid; idx < M_TOT; idx += stride) {
            unsigned long long key = make_key(__ldg(&scores[idx]), idx);
            int bk = (int)(key & 0xFFFull);
            int lo = soff[bk], hi = soff[bk + 1];
            while (lo < hi) {
                int mid = (lo + hi) >> 1;
                if (sk[mid] < key) lo = mid + 1; else hi = mid;
            }
            atomicAdd(&g_c[z][lo], 1);
        }
    }
    grid_sync_idx(2);

    // ========================= PHASE 4: FINAL (blocks 0,1) ==================
    // SMEM overlay: s_c[TMAX+1 (+pad)] | prec[TMAX]
    if (blockIdx.x < 2) {
        const int z = blockIdx.x;
        int*   s_c  = sm;
        float* prec = (float*)(sm + TMAX + 4);
        int*   wsum = wtot;                               // reuse static scan buffer

        int T = g_T[z];
        if (T == 0) { if (tid == 0) { out[z] = 0.0f; g_T[z] = 0; } return; }
        int bins = T + 1;

        __syncthreads();                                  // done with hist overlay
        for (int i = tid; i < bins; i += 1024) s_c[i] = g_c[z][i];
        __syncthreads();

        int CH = (bins + 1023) >> 10;
        int st = min(tid * CH, bins), en = min(st + CH, bins);

        // block-wide exclusive prefix sum of per-thread bin sums
        int ssum = 0;
        for (int p = st; p < en; ++p) ssum += s_c[p];
        int v = ssum;
#pragma unroll
        for (int d = 1; d < 32; d <<= 1) {
            int o = __shfl_up_sync(0xFFFFFFFFu, v, d);
            if (lane >= d) v += o;
        }
        if (lane == 31) wsum[warp] = v;
        __syncthreads();
        if (warp == 0) {
            int w = wsum[lane], wi = w;
#pragma unroll
            for (int d = 1; d < 32; d <<= 1) {
                int o = __shfl_up_sync(0xFFFFFFFFu, wi, d);
                if (lane >= d) wi += o;
            }
            wsum[lane] = wi - w;
        }
        __syncthreads();
        int C = wsum[warp] + (v - ssum);

        // precision values + chunk max
        float mx = 0.0f;
        for (int p = st; p < en; ++p) {
            C += s_c[p];
            if (p < T) {
                float pr = (float)(p + 1) / (float)C;
                prec[p] = pr;
                mx = fmaxf(mx, pr);
            }
        }

        // exclusive suffix-max over chunks (reversed exclusive max-scan)
        s_suf[1023 - tid] = mx;
        __syncthreads();
        float a = s_suf[tid], ai = a;
#pragma unroll
        for (int d = 1; d < 32; d <<= 1) {
            float o = __shfl_up_sync(0xFFFFFFFFu, ai, d);
            if (lane >= d) ai = fmaxf(ai, o);
        }
        float le = __shfl_up_sync(0xFFFFFFFFu, ai, 1);
        if (lane == 0) le = 0.0f;
        if (lane == 31) wmax[warp] = ai;
        __syncthreads();
        if (warp == 0) {
            float w0 = wmax[lane], wi = w0;
#pragma unroll
            for (int d = 1; d < 32; d <<= 1) {
                float o = __shfl_up_sync(0xFFFFFFFFu, wi, d);
                if (lane >= d) wi = fmaxf(wi, o);
            }
            float e = __shfl_up_sync(0xFFFFFFFFu, wi, 1);
            if (lane == 0) e = 0.0f;
            wmax[lane] = e;
            if (lane == 31) s_gmax = wi;                  // global max precision
        }
        __syncthreads();
        float suf_excl = fmaxf(wmax[warp], le);
        s_suf[tid] = suf_excl;
        __syncthreads();
        float run = s_suf[1023 - tid];
        __syncthreads();

        // weighted sum (descending within chunk, running suffix max)
        double s = 0.0;
        int hi = min(en, T);
        for (int p = hi - 1; p >= st; --p) {
            run = fmaxf(run, prec[p]);
            s += (double)run;
        }

        // double reduction
#pragma unroll
        for (int d = 16; d; d >>= 1) s += __shfl_down_sync(0xFFFFFFFFu, s, d);
        if (lane == 0) wdbl[warp] = s;
        __syncthreads();
        if (warp == 0) {
            double t = wdbl[lane];
#pragma unroll
            for (int d = 16; d; d >>= 1) t += __shfl_down_sync(0xFFFFFFFFu, t, d);
            if (lane == 0) {
                if (s_c[0] == 1) t -= (double)s_gmax;     // rank-0 TP excluded
                out[z] = (float)(t / (double)(BB * GG));
                g_T[z] = 0;                               // restore invariant for replay
            }
        }
    }
}

// ----------------------------------------------------------------------------
// Launcher (graph-capturable: a single kernel launch)
// ----------------------------------------------------------------------------
extern "C" void kernel_launch(void* const* d_in, const int* in_sizes, int n_in,
                              void* d_out, int out_size) {
    const float*  scores = (const float*)d_in[0];
    const float2* segs   = (const float2*)d_in[1];
    const float2* gts    = (const float2*)d_in[2];
    float* out = (float*)d_out;

    // max over phase overlays:
    //   greedy 90,000 | sort 135,184 | hist 118,792 | final 102,416
    const int smem_all = (2 * NBKT + 4) * 4 + TMAX * 8;   // 135,184 B

    cudaFuncSetAttribute(k_all, cudaFuncAttributeMaxDynamicSharedMemorySize, smem_all);
    cudaFuncSetAttribute(k_all, cudaFuncAttributePreferredSharedMemoryCarveout,
                         cudaSharedmemCarveoutMaxShared);

    k_all<<<GRID, 1024, smem_all>>>(segs, gts, scores, out);
}